// round 1
// baseline (speedup 1.0000x reference)
#include <cuda_runtime.h>
#include <cstdint>

// ---------------------------------------------------------------------------
// HTSubTree: out[b,o0,o1,o2,o3,r04] =
//   sum_{i,ranks} x[b,i0..i3] F0 F1 C02 F2 F3 C24 C04
// Restructured:
//   W01[(o01,r02)][i01]   = sum_{r01,r12} F0[i0,o0,r01] F1[i1,o1,r12] C02[r01,r12,r02]
//   W23[i23][(o23,r24)]   = sum_{r23,r34} F2[i2,o2,r23] F3[i3,o3,r34] C24[r23,r34,r24]
//   V[(r02,i23)][(o23,r04)] = sum_{r24} W23[i23][(o23,r24)] C04[r02,r24,r04]
//   T[b][(o01,r02)][i23]  = sum_{i01} W01[(o01,r02)][i01] x[b][i01][i23]
//   out[(b,o01)][(o23,r04)] = sum_{(r02,i23)} T * V      (plain GEMM 32768x512x512)
// ---------------------------------------------------------------------------

__device__ float g_W01t[512 * 64];    // [(o01*8+r02)][i01]
__device__ float g_W23[64 * 512];     // [i23][(o23*8+r24)]
__device__ float g_V[512 * 512];      // [(r02*64+i23)][(o23*8+r04)]
__device__ float g_T[32768 * 512];    // [(b*64+o01)][(r02*64+i23)]   64 MB scratch

// ---- packed f32x2 helpers -------------------------------------------------
__device__ __forceinline__ unsigned long long ffma2(unsigned long long a,
                                                    unsigned long long b,
                                                    unsigned long long c) {
    unsigned long long d;
    asm("fma.rn.f32x2 %0, %1, %2, %3;" : "=l"(d) : "l"(a), "l"(b), "l"(c));
    return d;
}
__device__ __forceinline__ unsigned long long pack_dup(float v) {
    unsigned long long r;
    asm("mov.b64 %0, {%1, %1};" : "=l"(r) : "f"(v));
    return r;
}

// ---------------------------------------------------------------------------
// prep_w: build W01t and W23 from factors/cores. grid 256 x 256 threads.
// factors: [p][in][out][r] strides (512,64,8,1). cores: [c][r][r][r] (512,64,8,1)
//   cores[0]=C04[r02][r24][r04], cores[1]=C02[r01][r12][r02], cores[2]=C24[r23][r34][r24]
// ---------------------------------------------------------------------------
__global__ void prep_w(const float* __restrict__ factors,
                       const float* __restrict__ cores) {
    __shared__ float sf[2048];
    __shared__ float sc[1536];
    int tid = threadIdx.x;
    for (int i = tid; i < 2048; i += 256) sf[i] = factors[i];
    for (int i = tid; i < 1536; i += 256) sc[i] = cores[i];
    __syncthreads();

    int e = blockIdx.x * 256 + tid;   // 0..65535
    if (e < 32768) {
        int row = e >> 6;             // o01*8 + r02
        int i01 = e & 63;
        int o01 = row >> 3, r02 = row & 7;
        int o0 = o01 >> 3, o1 = o01 & 7, i0 = i01 >> 3, i1 = i01 & 7;
        const float* F0 = sf + i0 * 64 + o0 * 8;
        const float* F1 = sf + 512 + i1 * 64 + o1 * 8;
        const float* C02 = sc + 512;
        float acc = 0.f;
        #pragma unroll
        for (int r01 = 0; r01 < 8; ++r01) {
            float s = 0.f;
            #pragma unroll
            for (int r12 = 0; r12 < 8; ++r12)
                s += F1[r12] * C02[r01 * 64 + r12 * 8 + r02];
            acc += F0[r01] * s;
        }
        g_W01t[e] = acc;
    } else {
        int e2 = e - 32768;           // i23*512 + o23*8 + r24
        int i23 = e2 >> 9;
        int rem = e2 & 511;
        int o23 = rem >> 3, r24 = rem & 7;
        int i2 = i23 >> 3, i3 = i23 & 7, o2 = o23 >> 3, o3 = o23 & 7;
        const float* F2 = sf + 1024 + i2 * 64 + o2 * 8;
        const float* F3 = sf + 1536 + i3 * 64 + o3 * 8;
        const float* C24 = sc + 1024;
        float acc = 0.f;
        #pragma unroll
        for (int r23 = 0; r23 < 8; ++r23) {
            float s = 0.f;
            #pragma unroll
            for (int r34 = 0; r34 < 8; ++r34)
                s += F3[r34] * C24[r23 * 64 + r34 * 8 + r24];
            acc += F2[r23] * s;
        }
        g_W23[e2] = acc;
    }
}

// ---------------------------------------------------------------------------
// prep_v: V[(r02*64+i23)][(o23*8+r04)] = sum_r24 W23[i23][(o23,r24)] C04[r02,r24,r04]
// grid 256 x 256 threads, 4 entries each.
// ---------------------------------------------------------------------------
__global__ void prep_v(const float* __restrict__ cores) {
    __shared__ float sC04[512];
    int tid = threadIdx.x;
    for (int i = tid; i < 512; i += 256) sC04[i] = cores[i];
    __syncthreads();

    int g = blockIdx.x * 256 + tid;
    #pragma unroll
    for (int j = 0; j < 4; ++j) {
        int v = g + j * 65536;                 // 0..262143
        int rowV = v >> 9;                     // r02*64 + i23
        int coln = v & 511;                    // o23*8 + r04
        int r02 = rowV >> 6, i23 = rowV & 63;
        int o23 = coln >> 3, r04 = coln & 7;
        const float* w = g_W23 + i23 * 512 + o23 * 8;
        const float* c = sC04 + r02 * 64 + r04;
        float acc = 0.f;
        #pragma unroll
        for (int r24 = 0; r24 < 8; ++r24) acc += w[r24] * c[r24 * 8];
        g_V[v] = acc;
    }
}

// ---------------------------------------------------------------------------
// ht_k1: T_b = W01t (512x64) @ X_b (64x64), batched over b.
// grid (4, 512): blockIdx.x = 128-row chunk, blockIdx.y = b. 256 threads.
// smem: Xs[64][64] (16KB) + Wt[64][128] (k-major transposed, 32KB) = 48KB
// micro-tile: 4 rows x 8 cols per thread, f32x2 packed along cols.
// ---------------------------------------------------------------------------
__global__ __launch_bounds__(256, 2) void ht_k1(const float* __restrict__ x) {
    extern __shared__ float sm1[];
    float* Xs = sm1;          // [64][64]
    float* Wt = sm1 + 4096;   // [64][128]
    const int tid = threadIdx.x;
    const int b = blockIdx.y;
    const int rbase = blockIdx.x * 128;

    // load X_b (contiguous copy)
    {
        const float4* xg = (const float4*)(x + (size_t)b * 4096);
        float4* xs4 = (float4*)Xs;
        #pragma unroll
        for (int i = 0; i < 4; ++i) xs4[tid + i * 256] = xg[tid + i * 256];
    }
    // load W01t rows [rbase, rbase+128), transposed into Wt[k][row]
    #pragma unroll
    for (int i = 0; i < 8; ++i) {
        int l = tid + i * 256;
        int rr = l >> 4;              // 0..127
        int kq = (l & 15) * 4;        // 0..60
        float4 w = *(const float4*)(g_W01t + (size_t)(rbase + rr) * 64 + kq);
        Wt[(kq + 0) * 128 + rr] = w.x;
        Wt[(kq + 1) * 128 + rr] = w.y;
        Wt[(kq + 2) * 128 + rr] = w.z;
        Wt[(kq + 3) * 128 + rr] = w.w;
    }
    __syncthreads();

    const int tx = tid & 7;           // col group: 8 cols
    const int ty = tid >> 3;          // row group: 0..31 -> 4 rows
    const int r0 = ty * 4, c0 = tx * 8;

    unsigned long long acc[4][4];
    #pragma unroll
    for (int r = 0; r < 4; ++r)
        #pragma unroll
        for (int c = 0; c < 4; ++c) acc[r][c] = 0ULL;

    #pragma unroll 8
    for (int kk = 0; kk < 64; ++kk) {
        float4 a0 = *(const float4*)(Wt + kk * 128 + r0);
        ulonglong2 b0 = *(const ulonglong2*)(Xs + kk * 64 + c0);
        ulonglong2 b1 = *(const ulonglong2*)(Xs + kk * 64 + c0 + 4);
        unsigned long long bq0 = b0.x, bq1 = b0.y, bq2 = b1.x, bq3 = b1.y;
        float av[4] = {a0.x, a0.y, a0.z, a0.w};
        #pragma unroll
        for (int r = 0; r < 4; ++r) {
            unsigned long long ap = pack_dup(av[r]);
            acc[r][0] = ffma2(ap, bq0, acc[r][0]);
            acc[r][1] = ffma2(ap, bq1, acc[r][1]);
            acc[r][2] = ffma2(ap, bq2, acc[r][2]);
            acc[r][3] = ffma2(ap, bq3, acc[r][3]);
        }
    }

    // store: T flat = b*32768 + row*64 + col, row = rbase + r0 + r, col = c0..
    float* Tg = g_T + (size_t)b * 32768 + (size_t)(rbase + r0) * 64 + c0;
    #pragma unroll
    for (int r = 0; r < 4; ++r) {
        *(ulonglong2*)(Tg + (size_t)r * 64)     = make_ulonglong2(acc[r][0], acc[r][1]);
        *(ulonglong2*)(Tg + (size_t)r * 64 + 4) = make_ulonglong2(acc[r][2], acc[r][3]);
    }
}

// ---------------------------------------------------------------------------
// ht_k2: out = T (32768x512) @ V (512x512). Row-major everywhere; C layout
// is exactly the required (B, o0,o1,o2,o3, r04) output.
// BM=128 BN=128 BK=16, 256 threads, 8x8 micro-tile, f32x2 packed cols,
// double-buffered smem.
// ---------------------------------------------------------------------------
#define BM 128
#define BN 128
#define BKK 16
#define ASTRIDE 132

__global__ __launch_bounds__(256, 2) void ht_k2(float* __restrict__ C) {
    extern __shared__ float sm2[];
    float* As = sm2;                         // [2][BKK][ASTRIDE]
    float* Bs = sm2 + 2 * BKK * ASTRIDE;     // [2][BKK][BN]

    const float* __restrict__ A = g_T;
    const float* __restrict__ Bm = g_V;

    const int tid = threadIdx.x;
    const int tx = tid & 15;                 // 0..15 -> 8 cols
    const int ty = tid >> 4;                 // 0..15 -> 8 rows
    const int mBase = blockIdx.y * BM;
    const int nBase = blockIdx.x * BN;

    const float* Ag = A + (size_t)mBase * 512;
    const float* Bg = Bm + nBase;

    unsigned long long acc[8][4];
    #pragma unroll
    for (int r = 0; r < 8; ++r)
        #pragma unroll
        for (int c = 0; c < 4; ++c) acc[r][c] = 0ULL;

    float4 pa[2], pb[2];

    // prologue: tile k0=0 -> buf 0
    #pragma unroll
    for (int i = 0; i < 2; ++i) {
        int l = tid + i * 256;
        int ar = l >> 2, ak = (l & 3) * 4;
        pa[i] = *(const float4*)(Ag + (size_t)ar * 512 + ak);
        int br = l >> 5, bc = (l & 31) * 4;
        pb[i] = *(const float4*)(Bg + (size_t)br * 512 + bc);
    }
    #pragma unroll
    for (int i = 0; i < 2; ++i) {
        int l = tid + i * 256;
        int ar = l >> 2, ak = (l & 3) * 4;
        As[(ak + 0) * ASTRIDE + ar] = pa[i].x;
        As[(ak + 1) * ASTRIDE + ar] = pa[i].y;
        As[(ak + 2) * ASTRIDE + ar] = pa[i].z;
        As[(ak + 3) * ASTRIDE + ar] = pa[i].w;
        int br = l >> 5, bc = (l & 31) * 4;
        *(float4*)(Bs + br * BN + bc) = pb[i];
    }
    __syncthreads();

    int buf = 0;
    for (int k0 = 0; k0 < 512; k0 += BKK) {
        const bool more = (k0 + BKK) < 512;
        if (more) {
            #pragma unroll
            for (int i = 0; i < 2; ++i) {
                int l = tid + i * 256;
                int ar = l >> 2, ak = (l & 3) * 4;
                pa[i] = *(const float4*)(Ag + (size_t)ar * 512 + (k0 + BKK + ak));
                int br = l >> 5, bc = (l & 31) * 4;
                pb[i] = *(const float4*)(Bg + (size_t)(k0 + BKK + br) * 512 + bc);
            }
        }
        const float* Ab = As + buf * (BKK * ASTRIDE);
        const float* Bb = Bs + buf * (BKK * BN);
        #pragma unroll
        for (int kk = 0; kk < BKK; ++kk) {
            float4 a0 = *(const float4*)(Ab + kk * ASTRIDE + ty * 8);
            float4 a1 = *(const float4*)(Ab + kk * ASTRIDE + ty * 8 + 4);
            ulonglong2 b0 = *(const ulonglong2*)(Bb + kk * BN + tx * 8);
            ulonglong2 b1 = *(const ulonglong2*)(Bb + kk * BN + tx * 8 + 4);
            unsigned long long bq0 = b0.x, bq1 = b0.y, bq2 = b1.x, bq3 = b1.y;
            float av[8] = {a0.x, a0.y, a0.z, a0.w, a1.x, a1.y, a1.z, a1.w};
            #pragma unroll
            for (int r = 0; r < 8; ++r) {
                unsigned long long ap = pack_dup(av[r]);
                acc[r][0] = ffma2(ap, bq0, acc[r][0]);
                acc[r][1] = ffma2(ap, bq1, acc[r][1]);
                acc[r][2] = ffma2(ap, bq2, acc[r][2]);
                acc[r][3] = ffma2(ap, bq3, acc[r][3]);
            }
        }
        if (more) {
            int nb = buf ^ 1;
            float* An = As + nb * (BKK * ASTRIDE);
            float* Bn = Bs + nb * (BKK * BN);
            __syncthreads();   // ensure all reads of current buf done before overwrite of other? (other buf idle) -> needed before reuse: nb buf was consumed 2 iters ago; safe to write only after all threads left it. One sync per iter suffices:
            #pragma unroll
            for (int i = 0; i < 2; ++i) {
                int l = tid + i * 256;
                int ar = l >> 2, ak = (l & 3) * 4;
                An[(ak + 0) * ASTRIDE + ar] = pa[i].x;
                An[(ak + 1) * ASTRIDE + ar] = pa[i].y;
                An[(ak + 2) * ASTRIDE + ar] = pa[i].z;
                An[(ak + 3) * ASTRIDE + ar] = pa[i].w;
                int br = l >> 5, bc = (l & 31) * 4;
                *(float4*)(Bn + br * BN + bc) = pb[i];
            }
            __syncthreads();
            buf = nb;
        }
    }

    // epilogue: C row = mBase + ty*8 + r, col = nBase + tx*8 + ...
    float* Cg = C + (size_t)(mBase + ty * 8) * 512 + nBase + tx * 8;
    #pragma unroll
    for (int r = 0; r < 8; ++r) {
        *(ulonglong2*)(Cg + (size_t)r * 512)     = make_ulonglong2(acc[r][0], acc[r][1]);
        *(ulonglong2*)(Cg + (size_t)r * 512 + 4) = make_ulonglong2(acc[r][2], acc[r][3]);
    }
}

// ---------------------------------------------------------------------------
extern "C" void kernel_launch(void* const* d_in, const int* in_sizes, int n_in,
                              void* d_out, int out_size) {
    (void)in_sizes; (void)n_in; (void)out_size;
    const float* x       = (const float*)d_in[0];
    const float* factors = (const float*)d_in[1];
    const float* cores   = (const float*)d_in[2];
    float* out = (float*)d_out;

    // smem sizes
    const int smem1 = (4096 + 64 * 128) * sizeof(float);            // 49152
    const int smem2 = (2 * BKK * ASTRIDE + 2 * BKK * BN) * sizeof(float); // 33280
    cudaFuncSetAttribute(ht_k1, cudaFuncAttributeMaxDynamicSharedMemorySize, smem1);
    cudaFuncSetAttribute(ht_k2, cudaFuncAttributeMaxDynamicSharedMemorySize, smem2);

    prep_w<<<256, 256>>>(factors, cores);
    prep_v<<<256, 256>>>(cores);
    ht_k1<<<dim3(4, 512), 256, smem1>>>(x);
    ht_k2<<<dim3(4, 256), 256, smem2>>>(out);
}

// round 4
// speedup vs baseline: 2.9551x; 2.9551x over previous
#include <cuda_runtime.h>
#include <cstdint>

// ---------------------------------------------------------------------------
// HTSubTree restructured:
//   W01t[(o01*8+r02)][i01]             (512 x 64)   prep_w   (tf32-rounded)
//   W23[i23][(o23*8+r24)]              (64 x 512)   prep_w   (fp32 temp)
//   Vt[n=(o23*8+r04)][k=(r02*64+i23)]  (512 x 512)  prep_v   (tf32-rounded)
//   T[b*64+o01][r02*64+i23] = W01t @ X_b            ht_k1m   (mma.sync tf32)
//   out[b*64+o01][n]        = T @ Vt^T              ht_k2m   (mma.sync tf32)
// mma.sync m16n8k8 row.col: A[m][k] row-major frags, B[n][k] (col-major k x n).
// ---------------------------------------------------------------------------

__device__ float g_W01t[512 * 64];
__device__ float g_W23[64 * 512];
__device__ float g_Vt[512 * 512];
__device__ float g_T[32768 * 512];

// ---------------- helpers --------------------------------------------------
__device__ __forceinline__ uint32_t smem_u32(const void* p) {
    uint32_t a;
    asm("{ .reg .u64 t; cvta.to.shared.u64 t, %1; cvt.u32.u64 %0, t; }" : "=r"(a) : "l"(p));
    return a;
}
__device__ __forceinline__ float tf32r(float f) {
    uint32_t u;
    asm("cvt.rna.tf32.f32 %0, %1;" : "=r"(u) : "f"(f));
    return __uint_as_float(u);
}
__device__ __forceinline__ void cp16(uint32_t s, const void* g) {
    asm volatile("cp.async.cg.shared.global [%0], [%1], 16;" :: "r"(s), "l"(g) : "memory");
}
__device__ __forceinline__ void cp_commit() { asm volatile("cp.async.commit_group;" ::: "memory"); }
__device__ __forceinline__ void cp_wait0()  { asm volatile("cp.async.wait_group 0;" ::: "memory"); }
__device__ __forceinline__ void cp_wait1()  { asm volatile("cp.async.wait_group 1;" ::: "memory"); }

__device__ __forceinline__ void mma8(float& d0, float& d1, float& d2, float& d3,
                                     uint32_t a0, uint32_t a1, uint32_t a2, uint32_t a3,
                                     uint32_t b0, uint32_t b1) {
    asm volatile(
        "mma.sync.aligned.m16n8k8.row.col.f32.tf32.tf32.f32 "
        "{%0,%1,%2,%3}, {%4,%5,%6,%7}, {%8,%9}, {%0,%1,%2,%3};"
        : "+f"(d0), "+f"(d1), "+f"(d2), "+f"(d3)
        : "r"(a0), "r"(a1), "r"(a2), "r"(a3), "r"(b0), "r"(b1));
}
__device__ __forceinline__ uint32_t f2u(float f) { return __float_as_uint(f); }

// ---------------------------------------------------------------------------
// prep_w: W01t (tf32) and W23 (fp32).
// factors [p][in][out][r] (512,64,8,1); cores: c0=C04, c1=C02, c2=C24
// ---------------------------------------------------------------------------
__global__ void prep_w(const float* __restrict__ factors,
                       const float* __restrict__ cores) {
    __shared__ float sf[2048];
    __shared__ float sc[1536];
    int tid = threadIdx.x;
    for (int i = tid; i < 2048; i += 256) sf[i] = factors[i];
    for (int i = tid; i < 1536; i += 256) sc[i] = cores[i];
    __syncthreads();

    int e = blockIdx.x * 256 + tid;
    if (e < 32768) {
        int row = e >> 6, i01 = e & 63;
        int o01 = row >> 3, r02 = row & 7;
        int o0 = o01 >> 3, o1 = o01 & 7, i0 = i01 >> 3, i1 = i01 & 7;
        const float* F0 = sf + i0 * 64 + o0 * 8;
        const float* F1 = sf + 512 + i1 * 64 + o1 * 8;
        const float* C02 = sc + 512;
        float acc = 0.f;
        #pragma unroll
        for (int r01 = 0; r01 < 8; ++r01) {
            float s = 0.f;
            #pragma unroll
            for (int r12 = 0; r12 < 8; ++r12)
                s += F1[r12] * C02[r01 * 64 + r12 * 8 + r02];
            acc += F0[r01] * s;
        }
        g_W01t[e] = tf32r(acc);
    } else {
        int e2 = e - 32768;
        int i23 = e2 >> 9, rem = e2 & 511;
        int o23 = rem >> 3, r24 = rem & 7;
        int i2 = i23 >> 3, i3 = i23 & 7, o2 = o23 >> 3, o3 = o23 & 7;
        const float* F2 = sf + 1024 + i2 * 64 + o2 * 8;
        const float* F3 = sf + 1536 + i3 * 64 + o3 * 8;
        const float* C24 = sc + 1024;
        float acc = 0.f;
        #pragma unroll
        for (int r23 = 0; r23 < 8; ++r23) {
            float s = 0.f;
            #pragma unroll
            for (int r34 = 0; r34 < 8; ++r34)
                s += F3[r34] * C24[r23 * 64 + r34 * 8 + r24];
            acc += F2[r23] * s;
        }
        g_W23[e2] = acc;
    }
}

// prep_v: Vt[n][k] = sum_r24 W23[i23][(o23,r24)] C04[r02,r24,r04] (tf32)
__global__ void prep_v(const float* __restrict__ cores) {
    __shared__ float sC04[512];
    int tid = threadIdx.x;
    for (int i = tid; i < 512; i += 256) sC04[i] = cores[i];
    __syncthreads();
    int g = blockIdx.x * 256 + tid;
    #pragma unroll
    for (int j = 0; j < 4; ++j) {
        int v = g + j * 65536;
        int kidx = v >> 9;          // r02*64 + i23
        int n    = v & 511;         // o23*8 + r04
        int r02 = kidx >> 6, i23 = kidx & 63;
        int o23 = n >> 3, r04 = n & 7;
        const float* w = g_W23 + i23 * 512 + o23 * 8;
        const float* c = sC04 + r02 * 64 + r04;
        float acc = 0.f;
        #pragma unroll
        for (int r24 = 0; r24 < 8; ++r24) acc += w[r24] * c[r24 * 8];
        g_Vt[(size_t)n * 512 + kidx] = tf32r(acc);
    }
}

// ---------------------------------------------------------------------------
// ht_k1m: T rows [mhalf*256, +256) for batch b = W01t-slice (256x64) @ X_b^T.
// grid (2, 512), 256 threads = 8 warps (4m x 2n), warp tile 64m x 32n.
// SMEM: As[256][72] swizzled, Bs[64][72] swizzled (X transposed, tf32).
// ---------------------------------------------------------------------------
#define K1_AS 0
#define K1_BS (256 * 72)
#define K1_SMEM ((256 * 72 + 64 * 72) * 4)

__global__ __launch_bounds__(256, 2) void ht_k1m(const float* __restrict__ x) {
    extern __shared__ float sm[];
    uint32_t sbase = smem_u32(sm);
    const int tid = threadIdx.x, wid = tid >> 5, lane = tid & 31;
    const int gid = lane >> 2, tig = lane & 3;
    const int wm = wid & 3, wn = wid >> 2;
    const int mhalf = blockIdx.x, b = blockIdx.y;

    // A = W01t rows [mhalf*256, +256): cp.async 16B, swizzle col'=(k+4*(row&7))&63
    const float* Ag = g_W01t + (size_t)(mhalf * 256) * 64;
    #pragma unroll
    for (int i = 0; i < 16; ++i) {
        int l = tid + i * 256;
        int row = l >> 4, kq = (l & 15) * 4;
        int col = (kq + 4 * (row & 7)) & 63;
        cp16(sbase + (K1_AS + row * 72 + col) * 4, Ag + row * 64 + kq);
    }
    cp_commit();
    // B[n=i23][k=i01] = X_b^T, tf32-rounded, same swizzle
    const float* xb = x + (size_t)b * 4096;
    #pragma unroll
    for (int i = 0; i < 16; ++i) {
        int l = tid + i * 256;
        int i01 = l >> 6, i23 = l & 63;
        float v = tf32r(__ldg(xb + i01 * 64 + i23));
        sm[K1_BS + i23 * 72 + ((i01 + 4 * (i23 & 7)) & 63)] = v;
    }
    cp_wait0();
    __syncthreads();

    float acc[4][4][4];
    #pragma unroll
    for (int mt = 0; mt < 4; ++mt)
        #pragma unroll
        for (int nt = 0; nt < 4; ++nt)
            #pragma unroll
            for (int q = 0; q < 4; ++q) acc[mt][nt][q] = 0.f;

    #pragma unroll
    for (int s = 0; s < 8; ++s) {
        const int k0 = s * 8;
        const int colA  = (k0 + tig + 4 * gid) & 63;
        const int colA4 = (colA + 4) & 63;
        uint32_t bf[4][2];
        #pragma unroll
        for (int nt = 0; nt < 4; ++nt) {
            int rB = K1_BS + (wn * 32 + nt * 8 + gid) * 72;
            bf[nt][0] = f2u(sm[rB + colA]);
            bf[nt][1] = f2u(sm[rB + colA4]);
        }
        #pragma unroll
        for (int mt = 0; mt < 4; ++mt) {
            int r0 = K1_AS + (wm * 64 + mt * 16 + gid) * 72;
            int r1 = r0 + 8 * 72;
            uint32_t a0 = f2u(sm[r0 + colA]);
            uint32_t a1 = f2u(sm[r1 + colA]);
            uint32_t a2 = f2u(sm[r0 + colA4]);
            uint32_t a3 = f2u(sm[r1 + colA4]);
            #pragma unroll
            for (int nt = 0; nt < 4; ++nt)
                mma8(acc[mt][nt][0], acc[mt][nt][1], acc[mt][nt][2], acc[mt][nt][3],
                     a0, a1, a2, a3, bf[nt][0], bf[nt][1]);
        }
    }

    // epilogue: tf32-round, store to g_T
    float* Tb = g_T + (size_t)b * 32768;
    #pragma unroll
    for (int mt = 0; mt < 4; ++mt) {
        int r0 = mhalf * 256 + wm * 64 + mt * 16 + gid;
        #pragma unroll
        for (int nt = 0; nt < 4; ++nt) {
            int col = wn * 32 + nt * 8 + 2 * tig;
            float2 v0 = make_float2(tf32r(acc[mt][nt][0]), tf32r(acc[mt][nt][1]));
            float2 v1 = make_float2(tf32r(acc[mt][nt][2]), tf32r(acc[mt][nt][3]));
            *(float2*)(Tb + (size_t)r0 * 64 + col)       = v0;
            *(float2*)(Tb + (size_t)(r0 + 8) * 64 + col) = v1;
        }
    }
}

// ---------------------------------------------------------------------------
// ht_k2m: out (32768x512) = T @ Vt^T.
// grid (4, 256), BM=128 BN=128 BK=32, 8 warps (4m x 2n), warp tile 32m x 64n.
// SMEM: 2 bufs x (As[128][40] + Bs[128][40]) swizzled, cp.async double-buffer.
// ---------------------------------------------------------------------------
#define K2_BUF 10240                 // floats per buffer (As 5120 + Bs 5120)
#define K2_SMEM (2 * K2_BUF * 4)

__device__ __forceinline__ void k2_load(float* sm, uint32_t sbase, int buf, int c,
                                        int mBase, int nBase, int tid) {
    const float* Ag = g_T  + (size_t)mBase * 512 + c * 32;
    const float* Bg = g_Vt + (size_t)nBase * 512 + c * 32;
    uint32_t ab = sbase + (buf * K2_BUF) * 4;
    uint32_t bb = ab + 5120 * 4;
    #pragma unroll
    for (int i = 0; i < 4; ++i) {
        int l = tid + i * 256;
        int row = l >> 3, kq = (l & 7) * 4;
        int col = (kq + 4 * (row & 7)) & 31;
        cp16(ab + (row * 40 + col) * 4, Ag + (size_t)row * 512 + kq);
        cp16(bb + (row * 40 + col) * 4, Bg + (size_t)row * 512 + kq);
    }
    cp_commit();
}

__global__ __launch_bounds__(256, 2) void ht_k2m(float* __restrict__ C) {
    extern __shared__ float sm[];
    uint32_t sbase = smem_u32(sm);
    const int tid = threadIdx.x, wid = tid >> 5, lane = tid & 31;
    const int gid = lane >> 2, tig = lane & 3;
    const int wm = wid & 3, wn = wid >> 2;
    const int mBase = blockIdx.y * 128, nBase = blockIdx.x * 128;

    float acc[2][8][4];
    #pragma unroll
    for (int mt = 0; mt < 2; ++mt)
        #pragma unroll
        for (int nt = 0; nt < 8; ++nt)
            #pragma unroll
            for (int q = 0; q < 4; ++q) acc[mt][nt][q] = 0.f;

    k2_load(sm, sbase, 0, 0, mBase, nBase, tid);
    k2_load(sm, sbase, 1, 1, mBase, nBase, tid);

    #pragma unroll 1
    for (int c = 0; c < 16; ++c) {
        const int buf = c & 1;
        if (c == 15) cp_wait0(); else cp_wait1();
        __syncthreads();
        const float* As = sm + buf * K2_BUF;
        const float* Bs = As + 5120;
        #pragma unroll
        for (int s = 0; s < 4; ++s) {
            const int k0 = s * 8;
            const int colA  = (k0 + tig + 4 * gid) & 31;
            const int colA4 = (colA + 4) & 31;
            uint32_t a[2][4];
            #pragma unroll
            for (int mt = 0; mt < 2; ++mt) {
                int r0 = (wm * 32 + mt * 16 + gid) * 40;
                int r1 = r0 + 8 * 40;
                a[mt][0] = f2u(As[r0 + colA]);
                a[mt][1] = f2u(As[r1 + colA]);
                a[mt][2] = f2u(As[r0 + colA4]);
                a[mt][3] = f2u(As[r1 + colA4]);
            }
            #pragma unroll
            for (int nt = 0; nt < 8; ++nt) {
                int rB = (wn * 64 + nt * 8 + gid) * 40;
                uint32_t b0 = f2u(Bs[rB + colA]);
                uint32_t b1 = f2u(Bs[rB + colA4]);
                #pragma unroll
                for (int mt = 0; mt < 2; ++mt)
                    mma8(acc[mt][nt][0], acc[mt][nt][1], acc[mt][nt][2], acc[mt][nt][3],
                         a[mt][0], a[mt][1], a[mt][2], a[mt][3], b0, b1);
            }
        }
        __syncthreads();
        if (c + 2 < 16) k2_load(sm, sbase, buf, c + 2, mBase, nBase, tid);
    }

    // epilogue
    #pragma unroll
    for (int mt = 0; mt < 2; ++mt) {
        int r0 = mBase + wm * 32 + mt * 16 + gid;
        #pragma unroll
        for (int nt = 0; nt < 8; ++nt) {
            int col = nBase + wn * 64 + nt * 8 + 2 * tig;
            *(float2*)(C + (size_t)r0 * 512 + col) =
                make_float2(acc[mt][nt][0], acc[mt][nt][1]);
            *(float2*)(C + (size_t)(r0 + 8) * 512 + col) =
                make_float2(acc[mt][nt][2], acc[mt][nt][3]);
        }
    }
}

// ---------------------------------------------------------------------------
extern "C" void kernel_launch(void* const* d_in, const int* in_sizes, int n_in,
                              void* d_out, int out_size) {
    (void)in_sizes; (void)n_in; (void)out_size;
    const float* x       = (const float*)d_in[0];
    const float* factors = (const float*)d_in[1];
    const float* cores   = (const float*)d_in[2];
    float* out = (float*)d_out;

    cudaFuncSetAttribute(ht_k1m, cudaFuncAttributeMaxDynamicSharedMemorySize, K1_SMEM);
    cudaFuncSetAttribute(ht_k2m, cudaFuncAttributeMaxDynamicSharedMemorySize, K2_SMEM);

    prep_w<<<256, 256>>>(factors, cores);
    prep_v<<<256, 256>>>(cores);
    ht_k1m<<<dim3(2, 512), 256, K1_SMEM>>>(x);
    ht_k2m<<<dim3(4, 256), 256, K2_SMEM>>>(out);
}

// round 5
// speedup vs baseline: 3.1282x; 1.0586x over previous
#include <cuda_runtime.h>
#include <cstdint>

// ---------------------------------------------------------------------------
// HTSubTree restructured:
//   W01t[(o01*8+r02)][i01]             (512 x 64)   prep_w   (tf32-rounded)
//   W23[i23][(o23*8+r24)]              (64 x 512)   prep_w   (fp32 temp)
//   Vt[n=(o23*8+r04)][k=(r02*64+i23)]  (512 x 512)  prep_v   (tf32-rounded)
//   T[b*64+o01][r02*64+i23] = W01t @ X_b            ht_k1m   (mma.sync tf32)
//   out[b*64+o01][n]        = T @ Vt^T              ht_k2m   (mma.sync tf32)
// mma.sync m16n8k8 row.col: A[m][k] row-major frags, B[n][k] (col-major k x n).
// ---------------------------------------------------------------------------

__device__ float g_W01t[512 * 64];
__device__ float g_W23[64 * 512];
__device__ float g_Vt[512 * 512];
__device__ float g_T[32768 * 512];

// ---------------- helpers --------------------------------------------------
__device__ __forceinline__ uint32_t smem_u32(const void* p) {
    uint32_t a;
    asm("{ .reg .u64 t; cvta.to.shared.u64 t, %1; cvt.u32.u64 %0, t; }" : "=r"(a) : "l"(p));
    return a;
}
__device__ __forceinline__ float tf32r(float f) {
    uint32_t u;
    asm("cvt.rna.tf32.f32 %0, %1;" : "=r"(u) : "f"(f));
    return __uint_as_float(u);
}
__device__ __forceinline__ void cp16(uint32_t s, const void* g) {
    asm volatile("cp.async.cg.shared.global [%0], [%1], 16;" :: "r"(s), "l"(g) : "memory");
}
__device__ __forceinline__ void cp_commit() { asm volatile("cp.async.commit_group;" ::: "memory"); }
__device__ __forceinline__ void cp_wait0()  { asm volatile("cp.async.wait_group 0;" ::: "memory"); }
__device__ __forceinline__ void cp_wait1()  { asm volatile("cp.async.wait_group 1;" ::: "memory"); }

__device__ __forceinline__ void mma8(float& d0, float& d1, float& d2, float& d3,
                                     uint32_t a0, uint32_t a1, uint32_t a2, uint32_t a3,
                                     uint32_t b0, uint32_t b1) {
    asm volatile(
        "mma.sync.aligned.m16n8k8.row.col.f32.tf32.tf32.f32 "
        "{%0,%1,%2,%3}, {%4,%5,%6,%7}, {%8,%9}, {%0,%1,%2,%3};"
        : "+f"(d0), "+f"(d1), "+f"(d2), "+f"(d3)
        : "r"(a0), "r"(a1), "r"(a2), "r"(a3), "r"(b0), "r"(b1));
}
__device__ __forceinline__ uint32_t f2u(float f) { return __float_as_uint(f); }

// ldmatrix on 32-bit data: an 8x8 b16 tile == 8x4 f32 tile; thread t receives
// f32 element (row t/4, col t%4) of the tile whose row pointers come from the
// address-providing lanes. x4 tiles ordered to match the mma A-fragment
// (a0,a1,a2,a3); x2 to match the B-fragment (b0,b1).
__device__ __forceinline__ void ldsm4(uint32_t& r0, uint32_t& r1, uint32_t& r2,
                                      uint32_t& r3, uint32_t addr) {
    asm volatile("ldmatrix.sync.aligned.m8n8.x4.shared.b16 {%0,%1,%2,%3}, [%4];"
                 : "=r"(r0), "=r"(r1), "=r"(r2), "=r"(r3) : "r"(addr));
}
__device__ __forceinline__ void ldsm2(uint32_t& r0, uint32_t& r1, uint32_t addr) {
    asm volatile("ldmatrix.sync.aligned.m8n8.x2.shared.b16 {%0,%1}, [%2];"
                 : "=r"(r0), "=r"(r1) : "r"(addr));
}

// ---------------------------------------------------------------------------
// prep_w: W01t (tf32) and W23 (fp32).
// factors [p][in][out][r] (512,64,8,1); cores: c0=C04, c1=C02, c2=C24
// ---------------------------------------------------------------------------
__global__ void prep_w(const float* __restrict__ factors,
                       const float* __restrict__ cores) {
    __shared__ float sf[2048];
    __shared__ float sc[1536];
    int tid = threadIdx.x;
    for (int i = tid; i < 2048; i += 256) sf[i] = factors[i];
    for (int i = tid; i < 1536; i += 256) sc[i] = cores[i];
    __syncthreads();

    int e = blockIdx.x * 256 + tid;
    if (e < 32768) {
        int row = e >> 6, i01 = e & 63;
        int o01 = row >> 3, r02 = row & 7;
        int o0 = o01 >> 3, o1 = o01 & 7, i0 = i01 >> 3, i1 = i01 & 7;
        const float* F0 = sf + i0 * 64 + o0 * 8;
        const float* F1 = sf + 512 + i1 * 64 + o1 * 8;
        const float* C02 = sc + 512;
        float acc = 0.f;
        #pragma unroll
        for (int r01 = 0; r01 < 8; ++r01) {
            float s = 0.f;
            #pragma unroll
            for (int r12 = 0; r12 < 8; ++r12)
                s += F1[r12] * C02[r01 * 64 + r12 * 8 + r02];
            acc += F0[r01] * s;
        }
        g_W01t[e] = tf32r(acc);
    } else {
        int e2 = e - 32768;
        int i23 = e2 >> 9, rem = e2 & 511;
        int o23 = rem >> 3, r24 = rem & 7;
        int i2 = i23 >> 3, i3 = i23 & 7, o2 = o23 >> 3, o3 = o23 & 7;
        const float* F2 = sf + 1024 + i2 * 64 + o2 * 8;
        const float* F3 = sf + 1536 + i3 * 64 + o3 * 8;
        const float* C24 = sc + 1024;
        float acc = 0.f;
        #pragma unroll
        for (int r23 = 0; r23 < 8; ++r23) {
            float s = 0.f;
            #pragma unroll
            for (int r34 = 0; r34 < 8; ++r34)
                s += F3[r34] * C24[r23 * 64 + r34 * 8 + r24];
            acc += F2[r23] * s;
        }
        g_W23[e2] = acc;
    }
}

// prep_v: Vt[n][k] = sum_r24 W23[i23][(o23,r24)] C04[r02,r24,r04] (tf32)
__global__ void prep_v(const float* __restrict__ cores) {
    __shared__ float sC04[512];
    int tid = threadIdx.x;
    for (int i = tid; i < 512; i += 256) sC04[i] = cores[i];
    __syncthreads();
    int g = blockIdx.x * 256 + tid;
    #pragma unroll
    for (int j = 0; j < 4; ++j) {
        int v = g + j * 65536;
        int kidx = v >> 9;          // r02*64 + i23
        int n    = v & 511;         // o23*8 + r04
        int r02 = kidx >> 6, i23 = kidx & 63;
        int o23 = n >> 3, r04 = n & 7;
        const float* w = g_W23 + i23 * 512 + o23 * 8;
        const float* c = sC04 + r02 * 64 + r04;
        float acc = 0.f;
        #pragma unroll
        for (int r24 = 0; r24 < 8; ++r24) acc += w[r24] * c[r24 * 8];
        g_Vt[(size_t)n * 512 + kidx] = tf32r(acc);
    }
}

// ---------------------------------------------------------------------------
// ht_k1m: T rows [mhalf*256, +256) for batch b = W01t-slice (256x64) @ X_b^T.
// grid (2, 512), 256 threads = 8 warps (4m x 2n), warp tile 64m x 32n.
// SMEM: As[256][72] swizzled, Bs[64][72] swizzled (X transposed, tf32).
// ---------------------------------------------------------------------------
#define K1_AS 0
#define K1_BS (256 * 72)
#define K1_SMEM ((256 * 72 + 64 * 72) * 4)

__global__ __launch_bounds__(256, 2) void ht_k1m(const float* __restrict__ x) {
    extern __shared__ float sm[];
    uint32_t sbase = smem_u32(sm);
    const int tid = threadIdx.x, wid = tid >> 5, lane = tid & 31;
    const int gid = lane >> 2, tig = lane & 3;
    const int wm = wid & 3, wn = wid >> 2;
    const int mhalf = blockIdx.x, b = blockIdx.y;

    // A = W01t rows [mhalf*256, +256): cp.async 16B, swizzle col'=(k+4*(row&7))&63
    const float* Ag = g_W01t + (size_t)(mhalf * 256) * 64;
    #pragma unroll
    for (int i = 0; i < 16; ++i) {
        int l = tid + i * 256;
        int row = l >> 4, kq = (l & 15) * 4;
        int col = (kq + 4 * (row & 7)) & 63;
        cp16(sbase + (K1_AS + row * 72 + col) * 4, Ag + row * 64 + kq);
    }
    cp_commit();
    // B[n=i23][k=i01] = X_b^T, tf32-rounded, same swizzle
    const float* xb = x + (size_t)b * 4096;
    #pragma unroll
    for (int i = 0; i < 16; ++i) {
        int l = tid + i * 256;
        int i01 = l >> 6, i23 = l & 63;
        float v = tf32r(__ldg(xb + i01 * 64 + i23));
        sm[K1_BS + i23 * 72 + ((i01 + 4 * (i23 & 7)) & 63)] = v;
    }
    cp_wait0();
    __syncthreads();

    float acc[4][4][4];
    #pragma unroll
    for (int mt = 0; mt < 4; ++mt)
        #pragma unroll
        for (int nt = 0; nt < 4; ++nt)
            #pragma unroll
            for (int q = 0; q < 4; ++q) acc[mt][nt][q] = 0.f;

    #pragma unroll
    for (int s = 0; s < 8; ++s) {
        const int k0 = s * 8;
        const int colA  = (k0 + tig + 4 * gid) & 63;
        const int colA4 = (colA + 4) & 63;
        uint32_t bf[4][2];
        #pragma unroll
        for (int nt = 0; nt < 4; ++nt) {
            int rB = K1_BS + (wn * 32 + nt * 8 + gid) * 72;
            bf[nt][0] = f2u(sm[rB + colA]);
            bf[nt][1] = f2u(sm[rB + colA4]);
        }
        #pragma unroll
        for (int mt = 0; mt < 4; ++mt) {
            int r0 = K1_AS + (wm * 64 + mt * 16 + gid) * 72;
            int r1 = r0 + 8 * 72;
            uint32_t a0 = f2u(sm[r0 + colA]);
            uint32_t a1 = f2u(sm[r1 + colA]);
            uint32_t a2 = f2u(sm[r0 + colA4]);
            uint32_t a3 = f2u(sm[r1 + colA4]);
            #pragma unroll
            for (int nt = 0; nt < 4; ++nt)
                mma8(acc[mt][nt][0], acc[mt][nt][1], acc[mt][nt][2], acc[mt][nt][3],
                     a0, a1, a2, a3, bf[nt][0], bf[nt][1]);
        }
    }

    // epilogue: tf32-round, store to g_T
    float* Tb = g_T + (size_t)b * 32768;
    #pragma unroll
    for (int mt = 0; mt < 4; ++mt) {
        int r0 = mhalf * 256 + wm * 64 + mt * 16 + gid;
        #pragma unroll
        for (int nt = 0; nt < 4; ++nt) {
            int col = wn * 32 + nt * 8 + 2 * tig;
            float2 v0 = make_float2(tf32r(acc[mt][nt][0]), tf32r(acc[mt][nt][1]));
            float2 v1 = make_float2(tf32r(acc[mt][nt][2]), tf32r(acc[mt][nt][3]));
            *(float2*)(Tb + (size_t)r0 * 64 + col)       = v0;
            *(float2*)(Tb + (size_t)(r0 + 8) * 64 + col) = v1;
        }
    }
}

// ---------------------------------------------------------------------------
// ht_k2m: out (32768x512) = T @ Vt^T.
// grid (4, 256), BM=128 BN=128 BK=32, 8 warps (4m x 2n), warp tile 32m x 64n.
// 3-stage cp.async pipeline, ONE __syncthreads per chunk.
// SMEM per stage: As[128][36] + Bs[128][36] (pad-4 rows: conflict-free LDSM).
// Fragments via ldmatrix (A: x4 per mt, B: x2 per nt).
// ---------------------------------------------------------------------------
#define K2_ASZ   4608                 // 128*36 floats
#define K2_STAGE (2 * K2_ASZ)         // floats per stage
#define K2_SMEM  (3 * K2_STAGE * 4)   // 110592 bytes

__device__ __forceinline__ void k2_load(uint32_t sbase, int stage, int c,
                                        int mBase, int nBase, int tid) {
    const float* Ag = g_T  + (size_t)mBase * 512 + c * 32;
    const float* Bg = g_Vt + (size_t)nBase * 512 + c * 32;
    uint32_t ab = sbase + (uint32_t)stage * (K2_STAGE * 4);
    uint32_t bb = ab + K2_ASZ * 4;
    #pragma unroll
    for (int i = 0; i < 4; ++i) {
        int l = tid + i * 256;
        int row = l >> 3, kq = (l & 7) * 4;
        cp16(ab + (row * 36 + kq) * 4, Ag + (size_t)row * 512 + kq);
        cp16(bb + (row * 36 + kq) * 4, Bg + (size_t)row * 512 + kq);
    }
    cp_commit();
}

__global__ __launch_bounds__(256, 2) void ht_k2m(float* __restrict__ C) {
    extern __shared__ float sm[];
    uint32_t sbase = smem_u32(sm);
    const int tid = threadIdx.x, wid = tid >> 5, lane = tid & 31;
    const int gid = lane >> 2, tig = lane & 3;
    const int wm = wid & 3, wn = wid >> 2;
    const int mBase = blockIdx.y * 128, nBase = blockIdx.x * 128;

    // ldmatrix lane addressing (byte offsets within a stage)
    // A x4: lanes 0-7 rows+0 k0, 8-15 rows+8 k0, 16-23 rows+0 k0+4, 24-31 rows+8 k0+4
    const uint32_t arow = (uint32_t)(wm * 32 + (lane & 7) + ((lane >> 3) & 1) * 8);
    const uint32_t aoff = (arow * 36 + (uint32_t)((lane >> 4) * 4)) * 4;
    // B x2: lanes 0-7 rows k0, lanes 8-15 rows k0+4
    const uint32_t brow = (uint32_t)(wn * 64 + (lane & 7));
    const uint32_t boff = K2_ASZ * 4 + (brow * 36 + (uint32_t)(((lane >> 3) & 1) * 4)) * 4;

    float acc[2][8][4];
    #pragma unroll
    for (int mt = 0; mt < 2; ++mt)
        #pragma unroll
        for (int nt = 0; nt < 8; ++nt)
            #pragma unroll
            for (int q = 0; q < 4; ++q) acc[mt][nt][q] = 0.f;

    k2_load(sbase, 0, 0, mBase, nBase, tid);
    k2_load(sbase, 1, 1, mBase, nBase, tid);

    #pragma unroll 1
    for (int c = 0; c < 16; ++c) {
        if (c == 15) cp_wait0(); else cp_wait1();
        __syncthreads();
        // stage (c+2)%3 was consumed at iteration c-1 -> free; load chunk c+2
        if (c + 2 < 16) k2_load(sbase, (c + 2) % 3, c + 2, mBase, nBase, tid);

        const uint32_t stb = sbase + (uint32_t)(c % 3) * (K2_STAGE * 4);
        const uint32_t ab = stb + aoff;
        const uint32_t bb = stb + boff;
        #pragma unroll
        for (int s = 0; s < 4; ++s) {
            const uint32_t kb = (uint32_t)(s * 8 * 4);
            uint32_t a[2][4];
            ldsm4(a[0][0], a[0][1], a[0][2], a[0][3], ab + kb);
            ldsm4(a[1][0], a[1][1], a[1][2], a[1][3], ab + kb + 16 * 36 * 4);
            #pragma unroll
            for (int nt = 0; nt < 8; ++nt) {
                uint32_t b0, b1;
                ldsm2(b0, b1, bb + kb + (uint32_t)(nt * 8 * 36 * 4));
                mma8(acc[0][nt][0], acc[0][nt][1], acc[0][nt][2], acc[0][nt][3],
                     a[0][0], a[0][1], a[0][2], a[0][3], b0, b1);
                mma8(acc[1][nt][0], acc[1][nt][1], acc[1][nt][2], acc[1][nt][3],
                     a[1][0], a[1][1], a[1][2], a[1][3], b0, b1);
            }
        }
    }

    // epilogue
    #pragma unroll
    for (int mt = 0; mt < 2; ++mt) {
        int r0 = mBase + wm * 32 + mt * 16 + gid;
        #pragma unroll
        for (int nt = 0; nt < 8; ++nt) {
            int col = nBase + wn * 64 + nt * 8 + 2 * tig;
            *(float2*)(C + (size_t)r0 * 512 + col) =
                make_float2(acc[mt][nt][0], acc[mt][nt][1]);
            *(float2*)(C + (size_t)(r0 + 8) * 512 + col) =
                make_float2(acc[mt][nt][2], acc[mt][nt][3]);
        }
    }
}

// ---------------------------------------------------------------------------
extern "C" void kernel_launch(void* const* d_in, const int* in_sizes, int n_in,
                              void* d_out, int out_size) {
    (void)in_sizes; (void)n_in; (void)out_size;
    const float* x       = (const float*)d_in[0];
    const float* factors = (const float*)d_in[1];
    const float* cores   = (const float*)d_in[2];
    float* out = (float*)d_out;

    cudaFuncSetAttribute(ht_k1m, cudaFuncAttributeMaxDynamicSharedMemorySize, K1_SMEM);
    cudaFuncSetAttribute(ht_k2m, cudaFuncAttributeMaxDynamicSharedMemorySize, K2_SMEM);

    prep_w<<<256, 256>>>(factors, cores);
    prep_v<<<256, 256>>>(cores);
    ht_k1m<<<dim3(2, 512), 256, K1_SMEM>>>(x);
    ht_k2m<<<dim3(4, 256), 256, K2_SMEM>>>(out);
}

// round 6
// speedup vs baseline: 5.1073x; 1.6327x over previous
#include <cuda_runtime.h>
#include <cuda_fp16.h>
#include <cstdint>

// ---------------------------------------------------------------------------
// HTSubTree restructured (fp16 storage, fp32 accumulation):
//   W01h[(o01*8+r02)][i01]             (512 x 64)   prep_w   (fp16)
//   W23[i23][(o23*8+r24)]              (64 x 512)   prep_w   (fp32 temp)
//   Vth[n=(o23*8+r04)][k=(r02*64+i23)] (512 x 512)  prep_v   (fp16, [n][k])
//   Th[b*64+o01][r02*64+i23] = W01h @ X_b           ht_k1m   (mma f16 k16)
//   out[b*64+o01][n]         = Th @ Vth^T           ht_k2m   (mma f16 k16)
// mma.sync m16n8k16 row.col: A[m][k] row-major, B stored [n][k] n-major.
// ---------------------------------------------------------------------------

__device__ __half g_W01h[512 * 64];
__device__ float  g_W23[64 * 512];
__device__ __half g_Vth[512 * 512];
__device__ __half g_Th[32768 * 512];

// ---------------- helpers --------------------------------------------------
__device__ __forceinline__ uint32_t smem_u32(const void* p) {
    uint32_t a;
    asm("{ .reg .u64 t; cvta.to.shared.u64 t, %1; cvt.u32.u64 %0, t; }" : "=r"(a) : "l"(p));
    return a;
}
__device__ __forceinline__ void cp16(uint32_t s, const void* g) {
    asm volatile("cp.async.cg.shared.global [%0], [%1], 16;" :: "r"(s), "l"(g) : "memory");
}
__device__ __forceinline__ void cp_commit() { asm volatile("cp.async.commit_group;" ::: "memory"); }
__device__ __forceinline__ void cp_wait0()  { asm volatile("cp.async.wait_group 0;" ::: "memory"); }
__device__ __forceinline__ void cp_wait1()  { asm volatile("cp.async.wait_group 1;" ::: "memory"); }

// fp16 mma, fp32 accumulate
__device__ __forceinline__ void mma16(float& d0, float& d1, float& d2, float& d3,
                                      uint32_t a0, uint32_t a1, uint32_t a2, uint32_t a3,
                                      uint32_t b0, uint32_t b1) {
    asm volatile(
        "mma.sync.aligned.m16n8k16.row.col.f32.f16.f16.f32 "
        "{%0,%1,%2,%3}, {%4,%5,%6,%7}, {%8,%9}, {%0,%1,%2,%3};"
        : "+f"(d0), "+f"(d1), "+f"(d2), "+f"(d3)
        : "r"(a0), "r"(a1), "r"(a2), "r"(a3), "r"(b0), "r"(b1));
}
__device__ __forceinline__ void ldsm4(uint32_t& r0, uint32_t& r1, uint32_t& r2,
                                      uint32_t& r3, uint32_t addr) {
    asm volatile("ldmatrix.sync.aligned.m8n8.x4.shared.b16 {%0,%1,%2,%3}, [%4];"
                 : "=r"(r0), "=r"(r1), "=r"(r2), "=r"(r3) : "r"(addr));
}

// ---------------------------------------------------------------------------
// prep_w: W01h (fp16) and W23 (fp32).
// factors [p][in][out][r] (512,64,8,1); cores: c0=C04, c1=C02, c2=C24
// ---------------------------------------------------------------------------
__global__ void prep_w(const float* __restrict__ factors,
                       const float* __restrict__ cores) {
    __shared__ float sf[2048];
    __shared__ float sc[1536];
    int tid = threadIdx.x;
    for (int i = tid; i < 2048; i += 256) sf[i] = factors[i];
    for (int i = tid; i < 1536; i += 256) sc[i] = cores[i];
    __syncthreads();

    int e = blockIdx.x * 256 + tid;
    if (e < 32768) {
        int row = e >> 6, i01 = e & 63;
        int o01 = row >> 3, r02 = row & 7;
        int o0 = o01 >> 3, o1 = o01 & 7, i0 = i01 >> 3, i1 = i01 & 7;
        const float* F0 = sf + i0 * 64 + o0 * 8;
        const float* F1 = sf + 512 + i1 * 64 + o1 * 8;
        const float* C02 = sc + 512;
        float acc = 0.f;
        #pragma unroll
        for (int r01 = 0; r01 < 8; ++r01) {
            float s = 0.f;
            #pragma unroll
            for (int r12 = 0; r12 < 8; ++r12)
                s += F1[r12] * C02[r01 * 64 + r12 * 8 + r02];
            acc += F0[r01] * s;
        }
        g_W01h[e] = __float2half_rn(acc);
    } else {
        int e2 = e - 32768;
        int i23 = e2 >> 9, rem = e2 & 511;
        int o23 = rem >> 3, r24 = rem & 7;
        int i2 = i23 >> 3, i3 = i23 & 7, o2 = o23 >> 3, o3 = o23 & 7;
        const float* F2 = sf + 1024 + i2 * 64 + o2 * 8;
        const float* F3 = sf + 1536 + i3 * 64 + o3 * 8;
        const float* C24 = sc + 1024;
        float acc = 0.f;
        #pragma unroll
        for (int r23 = 0; r23 < 8; ++r23) {
            float s = 0.f;
            #pragma unroll
            for (int r34 = 0; r34 < 8; ++r34)
                s += F3[r34] * C24[r23 * 64 + r34 * 8 + r24];
            acc += F2[r23] * s;
        }
        g_W23[e2] = acc;
    }
}

// prep_v: Vth[n][k] = sum_r24 W23[i23][(o23,r24)] C04[r02,r24,r04]  (fp16)
__global__ void prep_v(const float* __restrict__ cores) {
    __shared__ float sC04[512];
    int tid = threadIdx.x;
    for (int i = tid; i < 512; i += 256) sC04[i] = cores[i];
    __syncthreads();
    int g = blockIdx.x * 256 + tid;
    #pragma unroll
    for (int j = 0; j < 4; ++j) {
        int v = g + j * 65536;
        int kidx = v >> 9;          // r02*64 + i23
        int n    = v & 511;         // o23*8 + r04
        int r02 = kidx >> 6, i23 = kidx & 63;
        int o23 = n >> 3, r04 = n & 7;
        const float* w = g_W23 + i23 * 512 + o23 * 8;
        const float* c = sC04 + r02 * 64 + r04;
        float acc = 0.f;
        #pragma unroll
        for (int r24 = 0; r24 < 8; ++r24) acc += w[r24] * c[r24 * 8];
        g_Vth[(size_t)n * 512 + kidx] = __float2half_rn(acc);
    }
}

// ---------------------------------------------------------------------------
// ht_k1m: Th rows [mhalf*256,+256) for batch b = W01h-slice (256x64) @ X_b^T.
// grid (2, 512), 8 warps (4m x 2n), warp tile 64m x 32n, K=64 (4 k16-steps).
// SMEM (half): A[256][72], B[64][72]  (pad-8 rows -> conflict-free ldmatrix)
// ---------------------------------------------------------------------------
#define K1_AH   (256 * 72)                   // halves
#define K1_SMEM ((K1_AH + 64 * 72) * 2)      // 46080 bytes

__global__ __launch_bounds__(256, 2) void ht_k1m(const float* __restrict__ x) {
    extern __shared__ __half smh[];
    uint32_t sbase = smem_u32(smh);
    const int tid = threadIdx.x, wid = tid >> 5, lane = tid & 31;
    const int gid = lane >> 2, tig = lane & 3;
    const int wm = wid & 3, wn = wid >> 2;
    const int mhalf = blockIdx.x, b = blockIdx.y;

    // A = W01h rows [mhalf*256,+256): 128B/row via 8 cp16
    const __half* Ag = g_W01h + (size_t)(mhalf * 256) * 64;
    #pragma unroll
    for (int i = 0; i < 8; ++i) {
        int l = tid + i * 256;
        int row = l >> 3, s16 = (l & 7) * 8;          // halves
        cp16(sbase + (uint32_t)(row * 72 + s16) * 2, Ag + row * 64 + s16);
    }
    cp_commit();

    // B[n=i23][k=i01] = X_b^T, fp16. Each thread packs an i01-pair into half2.
    const float* xb = x + (size_t)b * 4096;
    __half* Bs = smh + K1_AH;
    #pragma unroll
    for (int i = 0; i < 8; ++i) {
        int l = tid + i * 256;
        int i23 = l & 63, i01p = (l >> 6) * 2;
        float v0 = __ldg(xb + i01p * 64 + i23);
        float v1 = __ldg(xb + (i01p + 1) * 64 + i23);
        *(__half2*)(Bs + i23 * 72 + i01p) = __floats2half2_rn(v0, v1);
    }
    cp_wait0();
    __syncthreads();

    // ldmatrix lane addressing (byte offsets)
    const uint32_t aoff = ((uint32_t)((wm * 64 + (lane & 7) + ((lane >> 3) & 1) * 8) * 72
                          + ((lane >> 4) & 1) * 8)) * 2;
    const uint32_t boff = (uint32_t)K1_AH * 2 +
                          ((uint32_t)((wn * 32 + (lane & 7) + ((lane >> 4) & 1) * 8) * 72
                          + ((lane >> 3) & 1) * 8)) * 2;

    float acc[4][4][4];
    #pragma unroll
    for (int mt = 0; mt < 4; ++mt)
        #pragma unroll
        for (int nt = 0; nt < 4; ++nt)
            #pragma unroll
            for (int q = 0; q < 4; ++q) acc[mt][nt][q] = 0.f;

    #pragma unroll
    for (int s = 0; s < 4; ++s) {
        const uint32_t kb = (uint32_t)(s * 16 * 2);     // 16 halves per step
        uint32_t a[4][4], bf[2][4];
        #pragma unroll
        for (int mt = 0; mt < 4; ++mt)
            ldsm4(a[mt][0], a[mt][1], a[mt][2], a[mt][3],
                  sbase + aoff + (uint32_t)(mt * 16 * 72 * 2) + kb);
        #pragma unroll
        for (int p = 0; p < 2; ++p)
            ldsm4(bf[p][0], bf[p][1], bf[p][2], bf[p][3],
                  sbase + boff + (uint32_t)(p * 16 * 72 * 2) + kb);
        #pragma unroll
        for (int mt = 0; mt < 4; ++mt)
            #pragma unroll
            for (int p = 0; p < 2; ++p) {
                mma16(acc[mt][2*p][0], acc[mt][2*p][1], acc[mt][2*p][2], acc[mt][2*p][3],
                      a[mt][0], a[mt][1], a[mt][2], a[mt][3], bf[p][0], bf[p][1]);
                mma16(acc[mt][2*p+1][0], acc[mt][2*p+1][1], acc[mt][2*p+1][2], acc[mt][2*p+1][3],
                      a[mt][0], a[mt][1], a[mt][2], a[mt][3], bf[p][2], bf[p][3]);
            }
    }

    // epilogue: fp16 pack, store to g_Th (flat (b*64+o01)*512 + r02*64+i23)
    __half* Tb = g_Th + (size_t)b * 32768;
    #pragma unroll
    for (int mt = 0; mt < 4; ++mt) {
        int r0 = mhalf * 256 + wm * 64 + mt * 16 + gid;
        #pragma unroll
        for (int nt = 0; nt < 4; ++nt) {
            int col = wn * 32 + nt * 8 + 2 * tig;
            *(__half2*)(Tb + (size_t)r0 * 64 + col) =
                __floats2half2_rn(acc[mt][nt][0], acc[mt][nt][1]);
            *(__half2*)(Tb + (size_t)(r0 + 8) * 64 + col) =
                __floats2half2_rn(acc[mt][nt][2], acc[mt][nt][3]);
        }
    }
}

// ---------------------------------------------------------------------------
// ht_k2m: out (32768x512 f32) = Th @ Vth^T.
// grid (4, 256), BM=128 BN=128 BK=64 (halves), 8 warps (4m x 2n),
// warp tile 32m x 64n, 3-stage cp.async, one __syncthreads per chunk.
// SMEM per stage (half): A[128][72] + B[128][72] = 36864 B.
// ---------------------------------------------------------------------------
#define K2_AH    (128 * 72)                  // halves per matrix per stage
#define K2_STAGE (2 * K2_AH * 2)             // bytes per stage = 36864
#define K2_SMEM  (3 * K2_STAGE)              // 110592 bytes

__device__ __forceinline__ void k2_load(uint32_t sbase, int stage, int c,
                                        int mBase, int nBase, int tid) {
    const __half* Ag = g_Th  + (size_t)mBase * 512 + c * 64;
    const __half* Bg = g_Vth + (size_t)nBase * 512 + c * 64;
    uint32_t ab = sbase + (uint32_t)stage * K2_STAGE;
    uint32_t bb = ab + (uint32_t)K2_AH * 2;
    #pragma unroll
    for (int i = 0; i < 4; ++i) {
        int l = tid + i * 256;
        int row = l >> 3, s16 = (l & 7) * 8;          // halves
        cp16(ab + (uint32_t)(row * 72 + s16) * 2, Ag + (size_t)row * 512 + s16);
        cp16(bb + (uint32_t)(row * 72 + s16) * 2, Bg + (size_t)row * 512 + s16);
    }
    cp_commit();
}

__global__ __launch_bounds__(256, 2) void ht_k2m(float* __restrict__ C) {
    extern __shared__ __half smh[];
    uint32_t sbase = smem_u32(smh);
    const int tid = threadIdx.x, wid = tid >> 5, lane = tid & 31;
    const int gid = lane >> 2, tig = lane & 3;
    const int wm = wid & 3, wn = wid >> 2;
    const int mBase = blockIdx.y * 128, nBase = blockIdx.x * 128;

    // ldmatrix lane addressing (byte offsets within a stage)
    const uint32_t aoff = ((uint32_t)((wm * 32 + (lane & 7) + ((lane >> 3) & 1) * 8) * 72
                          + ((lane >> 4) & 1) * 8)) * 2;
    const uint32_t boff = (uint32_t)K2_AH * 2 +
                          ((uint32_t)((wn * 64 + (lane & 7) + ((lane >> 4) & 1) * 8) * 72
                          + ((lane >> 3) & 1) * 8)) * 2;

    float acc[2][8][4];
    #pragma unroll
    for (int mt = 0; mt < 2; ++mt)
        #pragma unroll
        for (int nt = 0; nt < 8; ++nt)
            #pragma unroll
            for (int q = 0; q < 4; ++q) acc[mt][nt][q] = 0.f;

    k2_load(sbase, 0, 0, mBase, nBase, tid);
    k2_load(sbase, 1, 1, mBase, nBase, tid);

    #pragma unroll 1
    for (int c = 0; c < 8; ++c) {
        if (c == 7) cp_wait0(); else cp_wait1();
        __syncthreads();
        // stage (c+2)%3 was consumed at iteration c-1 -> free
        if (c + 2 < 8) k2_load(sbase, (c + 2) % 3, c + 2, mBase, nBase, tid);

        const uint32_t stb = sbase + (uint32_t)(c % 3) * K2_STAGE;
        const uint32_t ab = stb + aoff;
        const uint32_t bb = stb + boff;
        #pragma unroll
        for (int s = 0; s < 4; ++s) {
            const uint32_t kb = (uint32_t)(s * 16 * 2);
            uint32_t a[2][4], bf[4][4];
            ldsm4(a[0][0], a[0][1], a[0][2], a[0][3], ab + kb);
            ldsm4(a[1][0], a[1][1], a[1][2], a[1][3], ab + kb + 16 * 72 * 2);
            #pragma unroll
            for (int p = 0; p < 4; ++p)
                ldsm4(bf[p][0], bf[p][1], bf[p][2], bf[p][3],
                      bb + kb + (uint32_t)(p * 16 * 72 * 2));
            #pragma unroll
            for (int p = 0; p < 4; ++p) {
                #pragma unroll
                for (int mt = 0; mt < 2; ++mt) {
                    mma16(acc[mt][2*p][0], acc[mt][2*p][1], acc[mt][2*p][2], acc[mt][2*p][3],
                          a[mt][0], a[mt][1], a[mt][2], a[mt][3], bf[p][0], bf[p][1]);
                    mma16(acc[mt][2*p+1][0], acc[mt][2*p+1][1], acc[mt][2*p+1][2], acc[mt][2*p+1][3],
                          a[mt][0], a[mt][1], a[mt][2], a[mt][3], bf[p][2], bf[p][3]);
                }
            }
        }
    }

    // epilogue (fp32 out)
    #pragma unroll
    for (int mt = 0; mt < 2; ++mt) {
        int r0 = mBase + wm * 32 + mt * 16 + gid;
        #pragma unroll
        for (int nt = 0; nt < 8; ++nt) {
            int col = nBase + wn * 64 + nt * 8 + 2 * tig;
            *(float2*)(C + (size_t)r0 * 512 + col) =
                make_float2(acc[mt][nt][0], acc[mt][nt][1]);
            *(float2*)(C + (size_t)(r0 + 8) * 512 + col) =
                make_float2(acc[mt][nt][2], acc[mt][nt][3]);
        }
    }
}

// ---------------------------------------------------------------------------
extern "C" void kernel_launch(void* const* d_in, const int* in_sizes, int n_in,
                              void* d_out, int out_size) {
    (void)in_sizes; (void)n_in; (void)out_size;
    const float* x       = (const float*)d_in[0];
    const float* factors = (const float*)d_in[1];
    const float* cores   = (const float*)d_in[2];
    float* out = (float*)d_out;

    cudaFuncSetAttribute(ht_k1m, cudaFuncAttributeMaxDynamicSharedMemorySize, K1_SMEM);
    cudaFuncSetAttribute(ht_k2m, cudaFuncAttributeMaxDynamicSharedMemorySize, K2_SMEM);

    prep_w<<<256, 256>>>(factors, cores);
    prep_v<<<256, 256>>>(cores);
    ht_k1m<<<dim3(2, 512), 256, K1_SMEM>>>(x);
    ht_k2m<<<dim3(4, 256), 256, K2_SMEM>>>(out);
}